// round 7
// baseline (speedup 1.0000x reference)
#include <cuda_runtime.h>
#include <cuda_fp16.h>
#include <cstdint>

// ---------------------------------------------------------------- constants
#define B_     64
#define T_     16
#define IMG_   84
#define P_     7
#define NS_    144
#define K_     98
#define KP_    128          // K padded (pad halves stay zero)
#define E_     1024
#define NTOK_  1152
#define M_     73728

// Scratch (device globals, zero-init; k in [98,128) never written -> zero pad)
__device__ __half g_A[(size_t)M_ * KP_];   // [m][k]  18.9 MB
__device__ __half g_B[(size_t)E_ * KP_];   // [e][k]  256 KB

// ---------------------------------------------------------------- helpers
__device__ __forceinline__ void mma_f16(float4& d, const uint32_t a[4],
                                        const uint32_t b[2]) {
    asm("mma.sync.aligned.m16n8k16.row.col.f32.f16.f16.f32 "
        "{%0,%1,%2,%3}, {%4,%5,%6,%7}, {%8,%9}, {%0,%1,%2,%3};"
        : "+f"(d.x), "+f"(d.y), "+f"(d.z), "+f"(d.w)
        : "r"(a[0]), "r"(a[1]), "r"(a[2]), "r"(a[3]), "r"(b[0]), "r"(b[1]));
}
__device__ __forceinline__ uint32_t smem_u32(const void* p) {
    uint32_t a;
    asm("{ .reg .u64 t; cvta.to.shared.u64 t, %1; cvt.u32.u64 %0, t; }"
        : "=r"(a) : "l"(p));
    return a;
}
__device__ __forceinline__ void cpasync16(uint32_t dst, const void* src) {
    asm volatile("cp.async.cg.shared.global [%0], [%1], 16;"
                 :: "r"(dst), "l"(src));
}
#define CP_COMMIT() asm volatile("cp.async.commit_group;" ::: "memory")
#define CP_WAIT0()  asm volatile("cp.async.wait_group 0;" ::: "memory")

// ---------------------------------------------------------------- prep
// work unit = (token s, patch row pi): read 7 contiguous floats, write 7 halves
__global__ void gather_kernel(const float* __restrict__ video) {
    __shared__ float frame[IMG_ * IMG_];
    int bt = blockIdx.x, b = bt >> 4, t = bt & 15;
    const float* src = video + (size_t)bt * (IMG_ * IMG_);
    for (int i = threadIdx.x; i < IMG_ * IMG_; i += blockDim.x) frame[i] = src[i];
    __syncthreads();

    int d = t >> 1, ts = t & 1;
    int mbase = b * NTOK_ + d * NS_;
    for (int i = threadIdx.x; i < NS_ * P_; i += blockDim.x) {
        int s  = i / P_;
        int pi = i - s * P_;
        int h  = s / 12, w = s - h * 12;
        const float* fr = frame + (h * P_ + pi) * IMG_ + w * P_;
        __half* dst = g_A + (size_t)(mbase + s) * KP_ + ts * 49 + pi * P_;
#pragma unroll
        for (int pj = 0; pj < P_; ++pj)
            dst[pj] = __float2half_rn(fr[pj]);
    }
}

__global__ void wk_kernel(const float* __restrict__ W) {
    int idx = blockIdx.x * blockDim.x + threadIdx.x;
    if (idx >= E_ * K_) return;
    int e = idx / K_, k = idx - e * K_;
    g_B[(size_t)e * KP_ + k] = __float2half_rn(W[idx]);
}

// ---------------------------------------------------------------- GEMM
// CTA tile 128(m) x 128(e); 8 warps of 64x32. fp16 m16n8k16.
// K in 2 sequential chunks of 64 halves (single buffer) -> 37 KB smem,
// <=128 regs -> 2 CTAs/SM: cross-CTA overlap of compute and memory phases.
#define MT   128
#define ET   128
#define KC   64             // halves per chunk
#define SAW  72             // smem row stride (halves): 36 words, conflict-free
#define SAB  (MT * SAW)     // halves in A buffer
#define SBB  (ET * SAW)
#define SMEM_BYTES ((SAB + SBB) * 2)   // 36864 B

__global__ __launch_bounds__(256, 2)
void gemm_kernel(const float* __restrict__ bias,
                 const float* __restrict__ pos,
                 float* __restrict__ out) {
    extern __shared__ __half sm[];
    __half* sA = sm;                  // [128][SAW]
    __half* sB = sm + SAB;            // [128][SAW]
    const uint32_t sA_u = smem_u32(sA);
    const uint32_t sB_u = smem_u32(sB);

    const int tid  = threadIdx.x;
    const int lane = tid & 31;
    const int wid  = tid >> 5;
    const int grp  = lane >> 2;        // 0..7
    const int tg   = lane & 3;         // 0..3
    const int wm   = wid & 1;          // m-half     -> wm*64
    const int wn   = wid >> 1;         // e-quadrant -> wn*32

    const int e0 = blockIdx.x * ET;
    const int m0 = blockIdx.y * MT;

    const int rr = tid >> 3;           // 0..31 rows per pass
    const int ch = tid & 7;            // 16B chunk within 128B row

    const __half* gA = g_A + (size_t)m0 * KP_ + ch * 8;
    const __half* gB = g_B + (size_t)e0 * KP_ + ch * 8;

    auto stage = [&](int c) {
        const __half* a = gA + c * KC;
        uint32_t dA = sA_u + ch * 16;
#pragma unroll
        for (int p = 0; p < 4; ++p) {
            int row = p * 32 + rr;
            cpasync16(dA + row * (SAW * 2), a + (size_t)row * KP_);
        }
        const __half* b = gB + c * KC;
        uint32_t dB = sB_u + ch * 16;
#pragma unroll
        for (int p = 0; p < 4; ++p) {
            int row = p * 32 + rr;
            cpasync16(dB + row * (SAW * 2), b + (size_t)row * KP_);
        }
        CP_COMMIT();
    };

    float4 acc[4][4];
#pragma unroll
    for (int i = 0; i < 4; ++i)
#pragma unroll
        for (int j = 0; j < 4; ++j) acc[i][j] = make_float4(0.f, 0.f, 0.f, 0.f);

#pragma unroll
    for (int c = 0; c < 2; ++c) {
        stage(c);
        CP_WAIT0();
        __syncthreads();

#pragma unroll
        for (int ks = 0; ks < 4; ++ks) {
            const int ko = ks * 16 + tg * 2;
            uint32_t af[4][4], bf[4][2];
#pragma unroll
            for (int mf = 0; mf < 4; ++mf) {
                const __half* r0 = sA + (wm * 64 + mf * 16 + grp) * SAW + ko;
                af[mf][0] = *(const uint32_t*)r0;
                af[mf][1] = *(const uint32_t*)(r0 + 8 * SAW);
                af[mf][2] = *(const uint32_t*)(r0 + 8);
                af[mf][3] = *(const uint32_t*)(r0 + 8 * SAW + 8);
            }
#pragma unroll
            for (int nf = 0; nf < 4; ++nf) {
                const __half* r0 = sB + (wn * 32 + nf * 8 + grp) * SAW + ko;
                bf[nf][0] = *(const uint32_t*)r0;
                bf[nf][1] = *(const uint32_t*)(r0 + 8);
            }
#pragma unroll
            for (int mf = 0; mf < 4; ++mf)
#pragma unroll
                for (int nf = 0; nf < 4; ++nf)
                    mma_f16(acc[mf][nf], af[mf], bf[nf]);
        }
        __syncthreads();
    }

    // ---- epilogue: out = acc + bias + pos (MT=128 divides NTOK -> no wrap) ----
    const int n0 = m0 % NTOK_;
    float2 bb[4];
#pragma unroll
    for (int nf = 0; nf < 4; ++nf)
        bb[nf] = *(const float2*)(bias + e0 + wn * 32 + nf * 8 + tg * 2);

#pragma unroll
    for (int mf = 0; mf < 4; ++mf) {
        int rl = wm * 64 + mf * 16 + grp;
        const float* pr0 = pos + (size_t)(n0 + rl) * E_ + e0 + wn * 32 + tg * 2;
        const float* pr1 = pr0 + 8 * E_;
        float* or0 = out + (size_t)(m0 + rl) * E_ + e0 + wn * 32 + tg * 2;
        float* or1 = or0 + 8 * E_;
#pragma unroll
        for (int nf = 0; nf < 4; ++nf) {
            float2 p0 = *(const float2*)(pr0 + nf * 8);
            float2 p1 = *(const float2*)(pr1 + nf * 8);
            float4 a  = acc[mf][nf];
            float2 o0 = make_float2(a.x + bb[nf].x + p0.x, a.y + bb[nf].y + p0.y);
            float2 o1 = make_float2(a.z + bb[nf].x + p1.x, a.w + bb[nf].y + p1.y);
            __stcs((float2*)(or0 + nf * 8), o0);
            __stcs((float2*)(or1 + nf * 8), o1);
        }
    }
}

// ---------------------------------------------------------------- launch
extern "C" void kernel_launch(void* const* d_in, const int* in_sizes, int n_in,
                              void* d_out, int out_size) {
    const float* video = (const float*)d_in[0];   // [64,16,1,84,84]
    const float* W     = (const float*)d_in[1];   // [1024,98]
    const float* bias  = (const float*)d_in[2];   // [1024]
    const float* pos   = (const float*)d_in[3];   // [1,1152,1024]
    float* out         = (float*)d_out;           // [64,1152,1024]

    cudaFuncSetAttribute(gemm_kernel, cudaFuncAttributeMaxDynamicSharedMemorySize,
                         SMEM_BYTES);

    gather_kernel<<<B_ * T_, 256>>>(video);
    wk_kernel<<<(E_ * K_ + 255) / 256, 256>>>(W);
    gemm_kernel<<<dim3(E_ / ET, M_ / MT), 256, SMEM_BYTES>>>(bias, pos, out);
}

// round 8
// speedup vs baseline: 1.0919x; 1.0919x over previous
#include <cuda_runtime.h>
#include <cuda_fp16.h>
#include <cstdint>

// ---------------------------------------------------------------- constants
#define B_     64
#define T_     16
#define IMG_   84
#define P_     7
#define NS_    144
#define K_     98
#define KP_    128          // K padded (pad halves stay zero)
#define E_     1024
#define NTOK_  1152
#define M_     73728

// Swizzled scratch: within each 128-half row, 16B chunk c lives at c ^ (row&7).
// Zero-init device globals; k in [98,128) never written -> zero padding.
__device__ __half g_A[(size_t)M_ * KP_];   // [m][128]  18.9 MB
__device__ __half g_B[(size_t)E_ * KP_];   // [e][128]  256 KB

// ---------------------------------------------------------------- helpers
__device__ __forceinline__ void mma_f16(float4& d, const uint32_t a[4],
                                        const uint32_t b[2]) {
    asm("mma.sync.aligned.m16n8k16.row.col.f32.f16.f16.f32 "
        "{%0,%1,%2,%3}, {%4,%5,%6,%7}, {%8,%9}, {%0,%1,%2,%3};"
        : "+f"(d.x), "+f"(d.y), "+f"(d.z), "+f"(d.w)
        : "r"(a[0]), "r"(a[1]), "r"(a[2]), "r"(a[3]), "r"(b[0]), "r"(b[1]));
}
__device__ __forceinline__ uint32_t smem_u32(const void* p) {
    uint32_t a;
    asm("{ .reg .u64 t; cvta.to.shared.u64 t, %1; cvt.u32.u64 %0, t; }"
        : "=r"(a) : "l"(p));
    return a;
}
#define MBAR_INIT(mb, c) \
    asm volatile("mbarrier.init.shared.b64 [%0], %1;" \
                 :: "r"((uint32_t)(mb)), "r"((uint32_t)(c)) : "memory")
#define MBAR_EXPECT_TX(mb, n) \
    asm volatile("mbarrier.arrive.expect_tx.shared.b64 _, [%0], %1;" \
                 :: "r"((uint32_t)(mb)), "r"((uint32_t)(n)) : "memory")
#define MBAR_WAIT(mb) do {                                                        \
    uint32_t _mb = (uint32_t)(mb); uint32_t _done;                                \
    asm volatile("{\n\t.reg .pred p;\n\t"                                         \
        "mbarrier.try_wait.parity.acquire.cta.shared::cta.b64 p, [%1], 0;\n\t"    \
        "selp.b32 %0, 1, 0, p;\n\t}" : "=r"(_done) : "r"(_mb) : "memory");        \
    if (!_done) {                                                                 \
        asm volatile("{\n\t.reg .pred P1;\n\t"                                    \
            "WL_%=:\n\t"                                                          \
            "mbarrier.try_wait.parity.acquire.cta.shared::cta.b64 P1, [%0], 0, 0x989680;\n\t" \
            "@P1 bra.uni WD_%=;\n\t"                                              \
            "bra.uni WL_%=;\n\t"                                                  \
            "WD_%=:\n\t}" :: "r"(_mb) : "memory");                                \
    }                                                                             \
} while (0)
__device__ __forceinline__ void bulk_g2s(uint32_t dst, const void* src,
                                         uint32_t bytes, uint32_t mbar) {
    asm volatile(
        "cp.async.bulk.shared::cta.global.mbarrier::complete_tx::bytes "
        "[%0], [%1], %2, [%3];"
        :: "r"(dst), "l"(src), "r"(bytes), "r"(mbar) : "memory");
}

// ---------------------------------------------------------------- prep
// R5-style gather (21us known) + swizzled write index.
__global__ void gather_kernel(const float* __restrict__ video) {
    __shared__ float frame[IMG_ * IMG_];
    int bt = blockIdx.x, b = bt >> 4, t = bt & 15;
    const float* src = video + (size_t)bt * (IMG_ * IMG_);
    for (int i = threadIdx.x; i < IMG_ * IMG_; i += blockDim.x) frame[i] = src[i];
    __syncthreads();

    int d = t >> 1, ts = t & 1;
    int mbase = b * NTOK_ + d * NS_;
    for (int i = threadIdx.x; i < NS_ * 49; i += blockDim.x) {
        int s = i / 49, k = i - s * 49;
        int pi = k / P_, pj = k - pi * P_;
        int h = s / 12, w = s - h * 12;
        float v = frame[(h * P_ + pi) * IMG_ + (w * P_ + pj)];
        int kk = ts * 49 + k;
        int ph = (((kk >> 3) ^ (s & 7)) << 3) | (kk & 7);   // (mbase+s)&7 == s&7
        g_A[(size_t)(mbase + s) * KP_ + ph] = __float2half_rn(v);
    }
}

__global__ void wk_kernel(const float* __restrict__ W) {
    int idx = blockIdx.x * blockDim.x + threadIdx.x;
    if (idx >= E_ * K_) return;
    int e = idx / K_, k = idx - e * K_;
    int ph = (((k >> 3) ^ (e & 7)) << 3) | (k & 7);
    g_B[(size_t)e * KP_ + ph] = __float2half_rn(W[idx]);
}

// ---------------------------------------------------------------- GEMM
// CTA 256(m) x 128(e), 8 warps of 64x64, full K=128 staged via cp.async.bulk
// (1 B copy + 4 A-quarter copies, each with its own mbarrier). Swizzled smem.
#define MT   256
#define ET   128
#define SAB  (MT * KP_)             // halves in A tile (64 KB)
#define SBB  (ET * KP_)             // halves in B tile (32 KB)
#define SMEM_BYTES ((SAB + SBB) * 2)   // 98304 B

__global__ __launch_bounds__(256, 1)
void gemm_kernel(const float* __restrict__ bias,
                 const float* __restrict__ pos,
                 float* __restrict__ out) {
    extern __shared__ __half sm[];
    __half* sA = sm;                  // [256][128] swizzled rows
    __half* sB = sm + SAB;            // [128][128]
    __shared__ __align__(8) unsigned long long bars[5];

    const int tid  = threadIdx.x;
    const int lane = tid & 31;
    const int wid  = tid >> 5;
    const int grp  = lane >> 2;        // 0..7
    const int tg   = lane & 3;         // 0..3
    const int wm   = wid & 3;          // m-quarter -> wm*64
    const int wn   = wid >> 2;         // e-half    -> wn*64

    const int e0 = blockIdx.x * ET;
    const int m0 = blockIdx.y * MT;

    const uint32_t barB = smem_u32(&bars[0]);
    const uint32_t barA = smem_u32(&bars[1]);   // +8*q for quarter q

    if (tid == 0) {
#pragma unroll
        for (int q = 0; q < 5; ++q) MBAR_INIT(smem_u32(&bars[q]), 1);
    }
    __syncthreads();

    if (tid == 0) {
        MBAR_EXPECT_TX(barB, SBB * 2);
        bulk_g2s(smem_u32(sB), g_B + (size_t)e0 * KP_, SBB * 2, barB);
#pragma unroll
        for (int q = 0; q < 4; ++q) {
            MBAR_EXPECT_TX(barA + q * 8, 64 * KP_ * 2);
            bulk_g2s(smem_u32(sA) + q * 64 * KP_ * 2,
                     g_A + (size_t)(m0 + q * 64) * KP_,
                     64 * KP_ * 2, barA + q * 8);
        }
    }

    float4 acc[4][8];
#pragma unroll
    for (int i = 0; i < 4; ++i)
#pragma unroll
        for (int j = 0; j < 8; ++j) acc[i][j] = make_float4(0.f, 0.f, 0.f, 0.f);

    MBAR_WAIT(barB);
    MBAR_WAIT(barA + wm * 8);          // each warp needs only its A quarter

    const __half* wA = sA + (wm * 64 + grp) * KP_;        // rows (base&7)==grp
    const __half* wB = sB + (wn * 64 + grp) * KP_;

#pragma unroll
    for (int ks = 0; ks < 8; ++ks) {
        // swizzle-aware column offsets: chunk (2ks) and (2ks+1), XOR grp
        const int off0 = (((2 * ks)     ^ grp) << 3) + tg * 2;
        const int off1 = (((2 * ks + 1) ^ grp) << 3) + tg * 2;

        uint32_t af[4][4], bf[8][2];
#pragma unroll
        for (int mf = 0; mf < 4; ++mf) {
            const __half* r0 = wA + mf * 16 * KP_;
            af[mf][0] = *(const uint32_t*)(r0 + off0);
            af[mf][1] = *(const uint32_t*)(r0 + 8 * KP_ + off0);
            af[mf][2] = *(const uint32_t*)(r0 + off1);
            af[mf][3] = *(const uint32_t*)(r0 + 8 * KP_ + off1);
        }
#pragma unroll
        for (int nf = 0; nf < 8; ++nf) {
            const __half* r0 = wB + nf * 8 * KP_;
            bf[nf][0] = *(const uint32_t*)(r0 + off0);
            bf[nf][1] = *(const uint32_t*)(r0 + off1);
        }
#pragma unroll
        for (int mf = 0; mf < 4; ++mf)
#pragma unroll
            for (int nf = 0; nf < 8; ++nf)
                mma_f16(acc[mf][nf], af[mf], bf[nf]);
    }

    // ---- epilogue: out = acc + bias + pos (MT=256 can cross batch bound) ----
    const int n0 = m0 % NTOK_;
    float2 bb[8];
#pragma unroll
    for (int nf = 0; nf < 8; ++nf)
        bb[nf] = *(const float2*)(bias + e0 + wn * 64 + nf * 8 + tg * 2);

#pragma unroll
    for (int mf = 0; mf < 4; ++mf) {
        int rl = wm * 64 + mf * 16 + grp;
        int m  = m0 + rl;
        int n  = n0 + rl;        if (n  >= NTOK_) n  -= NTOK_;
        int n2 = n0 + rl + 8;    if (n2 >= NTOK_) n2 -= NTOK_;
        const float* pr0 = pos + (size_t)n  * E_ + e0 + wn * 64 + tg * 2;
        const float* pr1 = pos + (size_t)n2 * E_ + e0 + wn * 64 + tg * 2;
        float* or0 = out + (size_t)m * E_ + e0 + wn * 64 + tg * 2;
        float* or1 = or0 + 8 * E_;
#pragma unroll
        for (int nf = 0; nf < 8; ++nf) {
            float2 p0 = *(const float2*)(pr0 + nf * 8);
            float2 p1 = *(const float2*)(pr1 + nf * 8);
            float4 a  = acc[mf][nf];
            float2 o0 = make_float2(a.x + bb[nf].x + p0.x, a.y + bb[nf].y + p0.y);
            float2 o1 = make_float2(a.z + bb[nf].x + p1.x, a.w + bb[nf].y + p1.y);
            __stcs((float2*)(or0 + nf * 8), o0);
            __stcs((float2*)(or1 + nf * 8), o1);
        }
    }
}

// ---------------------------------------------------------------- launch
extern "C" void kernel_launch(void* const* d_in, const int* in_sizes, int n_in,
                              void* d_out, int out_size) {
    const float* video = (const float*)d_in[0];   // [64,16,1,84,84]
    const float* W     = (const float*)d_in[1];   // [1024,98]
    const float* bias  = (const float*)d_in[2];   // [1024]
    const float* pos   = (const float*)d_in[3];   // [1,1152,1024]
    float* out         = (float*)d_out;           // [64,1152,1024]

    cudaFuncSetAttribute(gemm_kernel, cudaFuncAttributeMaxDynamicSharedMemorySize,
                         SMEM_BYTES);

    gather_kernel<<<B_ * T_, 256>>>(video);
    wk_kernel<<<(E_ * K_ + 255) / 256, 256>>>(W);
    gemm_kernel<<<dim3(E_ / ET, M_ / MT), 256, SMEM_BYTES>>>(bias, pos, out);
}

// round 9
// speedup vs baseline: 1.2044x; 1.1030x over previous
#include <cuda_runtime.h>
#include <cuda_fp16.h>
#include <cstdint>

// ---------------------------------------------------------------- constants
#define B_     64
#define T_     16
#define IMG_   84
#define P_     7
#define NS_    144
#define K_     98
#define KP_    128          // physical row width (halves); logical K used = 112
#define KSTEPS 7            // 7 x k16 = 112 >= 98
#define E_     1024
#define NTOK_  1152
#define M_     73728

// Swizzled scratch: within each 128-half row, 16B chunk c lives at c ^ (row&7).
// Zero-init device globals; halves [98,128) never written -> zero padding.
__device__ __half g_A[(size_t)M_ * KP_];   // [m][128]  18.9 MB
__device__ __half g_B[(size_t)E_ * KP_];   // [e][128]  256 KB

// ---------------------------------------------------------------- helpers
__device__ __forceinline__ void mma_f16(float4& d, const uint32_t a[4],
                                        const uint32_t b[2]) {
    asm("mma.sync.aligned.m16n8k16.row.col.f32.f16.f16.f32 "
        "{%0,%1,%2,%3}, {%4,%5,%6,%7}, {%8,%9}, {%0,%1,%2,%3};"
        : "+f"(d.x), "+f"(d.y), "+f"(d.z), "+f"(d.w)
        : "r"(a[0]), "r"(a[1]), "r"(a[2]), "r"(a[3]), "r"(b[0]), "r"(b[1]));
}
__device__ __forceinline__ uint32_t smem_u32(const void* p) {
    uint32_t a;
    asm("{ .reg .u64 t; cvta.to.shared.u64 t, %1; cvt.u32.u64 %0, t; }"
        : "=r"(a) : "l"(p));
    return a;
}
#define MBAR_INIT(mb, c) \
    asm volatile("mbarrier.init.shared.b64 [%0], %1;" \
                 :: "r"((uint32_t)(mb)), "r"((uint32_t)(c)) : "memory")
#define MBAR_EXPECT_TX(mb, n) \
    asm volatile("mbarrier.arrive.expect_tx.shared.b64 _, [%0], %1;" \
                 :: "r"((uint32_t)(mb)), "r"((uint32_t)(n)) : "memory")
#define MBAR_WAIT(mb) do {                                                        \
    uint32_t _mb = (uint32_t)(mb); uint32_t _done;                                \
    asm volatile("{\n\t.reg .pred p;\n\t"                                         \
        "mbarrier.try_wait.parity.acquire.cta.shared::cta.b64 p, [%1], 0;\n\t"    \
        "selp.b32 %0, 1, 0, p;\n\t}" : "=r"(_done) : "r"(_mb) : "memory");        \
    if (!_done) {                                                                 \
        asm volatile("{\n\t.reg .pred P1;\n\t"                                    \
            "WL_%=:\n\t"                                                          \
            "mbarrier.try_wait.parity.acquire.cta.shared::cta.b64 P1, [%0], 0, 0x989680;\n\t" \
            "@P1 bra.uni WD_%=;\n\t"                                              \
            "bra.uni WL_%=;\n\t"                                                  \
            "WD_%=:\n\t}" :: "r"(_mb) : "memory");                                \
    }                                                                             \
} while (0)
__device__ __forceinline__ void bulk_g2s(uint32_t dst, const void* src,
                                         uint32_t bytes, uint32_t mbar) {
    asm volatile(
        "cp.async.bulk.shared::cta.global.mbarrier::complete_tx::bytes "
        "[%0], [%1], %2, [%3];"
        :: "r"(dst), "l"(src), "r"(bytes), "r"(mbar) : "memory");
}

// ---------------------------------------------------------------- prep
__global__ void gather_kernel(const float* __restrict__ video) {
    __shared__ float frame[IMG_ * IMG_];
    int bt = blockIdx.x, b = bt >> 4, t = bt & 15;
    const float* src = video + (size_t)bt * (IMG_ * IMG_);
    for (int i = threadIdx.x; i < IMG_ * IMG_; i += blockDim.x) frame[i] = src[i];
    __syncthreads();

    int d = t >> 1, ts = t & 1;
    int mbase = b * NTOK_ + d * NS_;
    for (int i = threadIdx.x; i < NS_ * 49; i += blockDim.x) {
        int s = i / 49, k = i - s * 49;
        int pi = k / P_, pj = k - pi * P_;
        int h = s / 12, w = s - h * 12;
        float v = frame[(h * P_ + pi) * IMG_ + (w * P_ + pj)];
        int kk = ts * 49 + k;
        int ph = (((kk >> 3) ^ (s & 7)) << 3) | (kk & 7);   // (mbase+s)&7 == s&7
        g_A[(size_t)(mbase + s) * KP_ + ph] = __float2half_rn(v);
    }
}

__global__ void wk_kernel(const float* __restrict__ W) {
    int idx = blockIdx.x * blockDim.x + threadIdx.x;
    if (idx >= E_ * K_) return;
    int e = idx / K_, k = idx - e * K_;
    int ph = (((k >> 3) ^ (e & 7)) << 3) | (k & 7);
    g_B[(size_t)e * KP_ + ph] = __float2half_rn(W[idx]);
}

// ---------------------------------------------------------------- GEMM
// CTA 256(m) x 128(e), 8 warps of 64x64. Full-K resident (bulk-staged,
// swizzled). Per warp: two n-halves, each = 7 ksteps of MMA then immediate
// epilogue store -> tensor and memory phases interleave across warps.
#define MT   256
#define ET   128
#define SAB  (MT * KP_)             // halves in A tile (64 KB)
#define SBB  (ET * KP_)             // halves in B tile (32 KB)
#define SMEM_BYTES ((SAB + SBB) * 2)   // 98304 B

__global__ __launch_bounds__(256, 1)
void gemm_kernel(const float* __restrict__ bias,
                 const float* __restrict__ pos,
                 float* __restrict__ out) {
    extern __shared__ __half sm[];
    __half* sA = sm;                  // [256][128] swizzled rows
    __half* sB = sm + SAB;            // [128][128]
    __shared__ __align__(8) unsigned long long bars[5];

    const int tid  = threadIdx.x;
    const int lane = tid & 31;
    const int wid  = tid >> 5;
    const int grp  = lane >> 2;        // 0..7
    const int tg   = lane & 3;         // 0..3
    const int wm   = wid & 3;          // m-quarter -> wm*64
    const int wn   = wid >> 2;         // e-half    -> wn*64

    const int e0 = blockIdx.x * ET;
    const int m0 = blockIdx.y * MT;

    const uint32_t barB = smem_u32(&bars[0]);
    const uint32_t barA = smem_u32(&bars[1]);   // +8*q for quarter q

    if (tid == 0) {
#pragma unroll
        for (int q = 0; q < 5; ++q) MBAR_INIT(smem_u32(&bars[q]), 1);
    }
    __syncthreads();

    if (tid == 0) {
        MBAR_EXPECT_TX(barB, SBB * 2);
        bulk_g2s(smem_u32(sB), g_B + (size_t)e0 * KP_, SBB * 2, barB);
#pragma unroll
        for (int q = 0; q < 4; ++q) {
            MBAR_EXPECT_TX(barA + q * 8, 64 * KP_ * 2);
            bulk_g2s(smem_u32(sA) + q * 64 * KP_ * 2,
                     g_A + (size_t)(m0 + q * 64) * KP_,
                     64 * KP_ * 2, barA + q * 8);
        }
    }

    MBAR_WAIT(barB);
    MBAR_WAIT(barA + wm * 8);          // each warp needs only its A quarter

    const __half* wA = sA + (wm * 64 + grp) * KP_;
    const __half* wB = sB + (wn * 64 + grp) * KP_;

    // epilogue coordinates shared by both halves
    const int n0 = m0 % NTOK_;
    int rl[4], mg[4], ng0[4], ng1[4];
#pragma unroll
    for (int mf = 0; mf < 4; ++mf) {
        rl[mf] = wm * 64 + mf * 16 + grp;
        mg[mf] = m0 + rl[mf];
        int n  = n0 + rl[mf];      if (n  >= NTOK_) n  -= NTOK_;
        int n2 = n0 + rl[mf] + 8;  if (n2 >= NTOK_) n2 -= NTOK_;
        ng0[mf] = n; ng1[mf] = n2;
    }

#pragma unroll
    for (int half = 0; half < 2; ++half) {
        const int nb = half * 4;                 // nf block base (4 per half)
        float4 acc[4][4];
#pragma unroll
        for (int i = 0; i < 4; ++i)
#pragma unroll
            for (int j = 0; j < 4; ++j) acc[i][j] = make_float4(0.f, 0.f, 0.f, 0.f);

#pragma unroll
        for (int ks = 0; ks < KSTEPS; ++ks) {
            const int off0 = (((2 * ks)     ^ grp) << 3) + tg * 2;
            const int off1 = (((2 * ks + 1) ^ grp) << 3) + tg * 2;

            uint32_t af[4][4], bf[4][2];
#pragma unroll
            for (int mf = 0; mf < 4; ++mf) {
                const __half* r0 = wA + mf * 16 * KP_;
                af[mf][0] = *(const uint32_t*)(r0 + off0);
                af[mf][1] = *(const uint32_t*)(r0 + 8 * KP_ + off0);
                af[mf][2] = *(const uint32_t*)(r0 + off1);
                af[mf][3] = *(const uint32_t*)(r0 + 8 * KP_ + off1);
            }
#pragma unroll
            for (int nf = 0; nf < 4; ++nf) {
                const __half* r0 = wB + (nb + nf) * 8 * KP_;
                bf[nf][0] = *(const uint32_t*)(r0 + off0);
                bf[nf][1] = *(const uint32_t*)(r0 + off1);
            }
#pragma unroll
            for (int mf = 0; mf < 4; ++mf)
#pragma unroll
                for (int nf = 0; nf < 4; ++nf)
                    mma_f16(acc[mf][nf], af[mf], bf[nf]);
        }

        // epilogue for this n-half: out = acc + bias + pos
        const int colb = e0 + wn * 64 + nb * 8 + tg * 2;
#pragma unroll
        for (int mf = 0; mf < 4; ++mf) {
            const float* pr0 = pos + (size_t)ng0[mf] * E_ + colb;
            const float* pr1 = pos + (size_t)ng1[mf] * E_ + colb;
            float* or0 = out + (size_t)mg[mf] * E_ + colb;
            float* or1 = or0 + 8 * E_;
#pragma unroll
            for (int nf = 0; nf < 4; ++nf) {
                float2 bb = *(const float2*)(bias + colb + nf * 8);
                float2 p0 = *(const float2*)(pr0 + nf * 8);
                float2 p1 = *(const float2*)(pr1 + nf * 8);
                float4 a  = acc[mf][nf];
                float2 o0 = make_float2(a.x + bb.x + p0.x, a.y + bb.y + p0.y);
                float2 o1 = make_float2(a.z + bb.x + p1.x, a.w + bb.y + p1.y);
                __stcs((float2*)(or0 + nf * 8), o0);
                __stcs((float2*)(or1 + nf * 8), o1);
            }
        }
    }
}

// ---------------------------------------------------------------- launch
extern "C" void kernel_launch(void* const* d_in, const int* in_sizes, int n_in,
                              void* d_out, int out_size) {
    const float* video = (const float*)d_in[0];   // [64,16,1,84,84]
    const float* W     = (const float*)d_in[1];   // [1024,98]
    const float* bias  = (const float*)d_in[2];   // [1024]
    const float* pos   = (const float*)d_in[3];   // [1,1152,1024]
    float* out         = (float*)d_out;           // [64,1152,1024]

    cudaFuncSetAttribute(gemm_kernel, cudaFuncAttributeMaxDynamicSharedMemorySize,
                         SMEM_BYTES);

    gather_kernel<<<B_ * T_, 256>>>(video);
    wk_kernel<<<(E_ * K_ + 255) / 256, 256>>>(W);
    gemm_kernel<<<dim3(E_ / ET, M_ / MT), 256, SMEM_BYTES>>>(bias, pos, out);
}